// round 1
// baseline (speedup 1.0000x reference)
#include <cuda_runtime.h>

// Problem constants (fixed by the dataset)
#define BB 8
#define CI 32
#define CO 64
#define FF 4
#define HH 64
#define WW 64

// Scratch (allocation-free rule: __device__ globals)
__device__ float g_iv[BB * CI];
__device__ float g_j0[BB * CI];
__device__ float g_j1[BB * CI];
__device__ float g_s0[BB * CO];
__device__ float g_s1[BB * CO];
__device__ float g_c [BB * CO];

// ---------------------------------------------------------------------------
// Kernel 1: per-(b,i) weighted reductions over the HxW plane.
//   iv = dx^2 * sum c_h c_w * v
//   j0 = dx^2 * sum c_h c_w * vc_x * v
//   j1 = dx^2 * sum c_h c_w * vc_y * v
// 256 blocks (one per (b,i)), 256 threads, 16 elems/thread, coalesced.
// ---------------------------------------------------------------------------
__global__ __launch_bounds__(256) void frl_reduce(
    const float* __restrict__ v, const float* __restrict__ vc)
{
    const int bi = blockIdx.x;
    const float* __restrict__ plane = v + (size_t)bi * (HH * WW);
    const int tid = threadIdx.x;

    float s = 0.f, sx = 0.f, sy = 0.f;
#pragma unroll
    for (int k = 0; k < 16; ++k) {
        const int idx = tid + k * 256;
        const int h = idx >> 6;
        const int w = idx & 63;
        float c = ((h == 0 || h == HH - 1) ? 0.5f : 1.0f)
                * ((w == 0 || w == WW - 1) ? 0.5f : 1.0f);
        const float val = c * plane[idx];
        const float x = vc[2 * idx + 0];
        const float y = vc[2 * idx + 1];
        s  += val;
        sx += val * x;
        sy += val * y;
    }
    // warp reduce
#pragma unroll
    for (int o = 16; o > 0; o >>= 1) {
        s  += __shfl_down_sync(0xffffffffu, s,  o);
        sx += __shfl_down_sync(0xffffffffu, sx, o);
        sy += __shfl_down_sync(0xffffffffu, sy, o);
    }
    __shared__ float sm[3][8];
    const int wid = tid >> 5, lid = tid & 31;
    if (lid == 0) { sm[0][wid] = s; sm[1][wid] = sx; sm[2][wid] = sy; }
    __syncthreads();
    if (tid == 0) {
        float a = 0.f, b = 0.f, cc = 0.f;
#pragma unroll
        for (int i = 0; i < 8; ++i) { a += sm[0][i]; b += sm[1][i]; cc += sm[2][i]; }
        const float dx = vc[2] - vc[0];   // v_coords[0,1,0] - v_coords[0,0,0]
        const float d2 = dx * dx;
        g_iv[bi] = a  * d2;
        g_j0[bi] = b  * d2;
        g_j1[bi] = cc * d2;
    }
}

// ---------------------------------------------------------------------------
// Kernel 2: tiny contraction. One block, 512 threads (= B*CO).
//   A[o,i,d]  = sum_f Wx[f,o,i,d]   (in smem)
//   Ay[o,i,d] = sum_f Wy[f,o,i,d]
//   S_d[b,o]  = sum_i A[o,i,d] * iv[b,i]
//   C[b,o]    = sum_{i,d} Ay[o,i,d] * J_d[b,i]
// ---------------------------------------------------------------------------
__global__ __launch_bounds__(512) void frl_combine(
    const float* __restrict__ Wx, const float* __restrict__ Wy)
{
    __shared__ float A [CO * CI * 2];   // 16 KB
    __shared__ float Ay[CO * CI * 2];   // 16 KB
    __shared__ float iv[BB * CI], j0[BB * CI], j1[BB * CI];

    const int tid = threadIdx.x;
    const int FSTR = CO * CI * 2;       // f-stride in Wx/Wy

    for (int k = tid; k < CO * CI * 2; k += 512) {
        float a = 0.f, ay = 0.f;
#pragma unroll
        for (int f = 0; f < FF; ++f) {
            a  += Wx[f * FSTR + k];
            ay += Wy[f * FSTR + k];
        }
        A[k] = a; Ay[k] = ay;
    }
    if (tid < BB * CI) {
        iv[tid] = g_iv[tid];
        j0[tid] = g_j0[tid];
        j1[tid] = g_j1[tid];
    }
    __syncthreads();

    const int b = tid >> 6;
    const int o = tid & 63;
    float s0 = 0.f, s1 = 0.f, c = 0.f;
#pragma unroll
    for (int i = 0; i < CI; ++i) {
        const float ivv = iv[b * CI + i];
        const float a0 = A [(o * CI + i) * 2 + 0];
        const float a1 = A [(o * CI + i) * 2 + 1];
        const float y0 = Ay[(o * CI + i) * 2 + 0];
        const float y1 = Ay[(o * CI + i) * 2 + 1];
        s0 += a0 * ivv;
        s1 += a1 * ivv;
        c  += y0 * j0[b * CI + i] + y1 * j1[b * CI + i];
    }
    g_s0[tid] = s0;
    g_s1[tid] = s1;
    g_c [tid] = c;
}

// ---------------------------------------------------------------------------
// Kernel 3: broadcast fill.
//   out[b,o,h,w] = S0[b,o]*tc_x + S1[b,o]*tc_y + C[b,o]
// 2048 blocks x 256 threads, one float4 store per thread (8 MB write).
// target_coords read as interleaved float4 pairs (32 KB, L2-resident).
// ---------------------------------------------------------------------------
__global__ __launch_bounds__(256) void frl_fill(
    const float* __restrict__ tc, float* __restrict__ out)
{
    const int g  = blockIdx.x * 256 + threadIdx.x;  // 0..524287
    const int bo = g >> 10;                          // plane index (b*CO+o)
    const int p  = g & 1023;                         // float4 index within HxW

    const float4* __restrict__ tc4 = reinterpret_cast<const float4*>(tc);
    const float4 t0 = __ldg(&tc4[p * 2 + 0]);        // (x0,y0,x1,y1)
    const float4 t1 = __ldg(&tc4[p * 2 + 1]);        // (x2,y2,x3,y3)

    const float s0 = g_s0[bo];
    const float s1 = g_s1[bo];
    const float c  = g_c [bo];

    float4 r;
    r.x = fmaf(s0, t0.x, fmaf(s1, t0.y, c));
    r.y = fmaf(s0, t0.z, fmaf(s1, t0.w, c));
    r.z = fmaf(s0, t1.x, fmaf(s1, t1.y, c));
    r.w = fmaf(s0, t1.z, fmaf(s1, t1.w, c));

    reinterpret_cast<float4*>(out)[g] = r;
}

extern "C" void kernel_launch(void* const* d_in, const int* in_sizes, int n_in,
                              void* d_out, int out_size)
{
    const float* v   = (const float*)d_in[0];   // [B,CI,H,W]
    const float* vc  = (const float*)d_in[1];   // [H,W,2]
    const float* tc  = (const float*)d_in[2];   // [H,W,2]
    const float* Wx  = (const float*)d_in[3];   // [F,CO,CI,2]
    const float* Wy  = (const float*)d_in[4];   // [F,CO,CI,2]
    float* out = (float*)d_out;                  // [B,CO,H,W]

    (void)in_sizes; (void)n_in; (void)out_size;

    frl_reduce <<<BB * CI, 256>>>(v, vc);
    frl_combine<<<1, 512>>>(Wx, Wy);
    frl_fill   <<<(BB * CO * HH * WW) / (4 * 256), 256>>>(tc, out);
}

// round 2
// speedup vs baseline: 2.3763x; 2.3763x over previous
#include <cuda_runtime.h>

// Problem constants (fixed by the dataset)
#define BB 8
#define CI 32
#define CO 64
#define FF 4
#define HH 64
#define WW 64

// Scratch (allocation-free rule: __device__ globals)
__device__ float g_iv[BB * CI];
__device__ float g_j0[BB * CI];
__device__ float g_j1[BB * CI];

// ---------------------------------------------------------------------------
// Kernel 1: per-(b,i) weighted reductions over the HxW plane.
// Exploits separable uniform grid: vc[h,w,0] = x0 + w*dx, vc[h,w,1] = y0 + h*dy
//   s  = sum c_h c_w * v
//   sw = sum c_h c_w * w * v      (-> j0 = d2*(x0*s + dx*sw))
//   sh = sum c_h c_w * h * v      (-> j1 = d2*(y0*s + dy*sh))
// 256 blocks (one per (b,i)), 256 threads, 4 float4 loads/thread, no vc loads
// in the hot loop.
// ---------------------------------------------------------------------------
__global__ __launch_bounds__(256) void frl_reduce(
    const float* __restrict__ v, const float* __restrict__ vc)
{
    const int bi = blockIdx.x;
    const float4* __restrict__ plane =
        reinterpret_cast<const float4*>(v + (size_t)bi * (HH * WW));
    const int tid = threadIdx.x;

    float s = 0.f, sw = 0.f, sh = 0.f;
#pragma unroll
    for (int k = 0; k < 4; ++k) {
        const int q = tid + k * 256;      // float4 index within plane, 0..1023
        const float4 t = plane[q];
        const int h  = q >> 4;            // 16 float4 per row of 64
        const int wq = q & 15;
        const float ch = (h == 0 || h == HH - 1) ? 0.5f : 1.0f;
        const float c0 = ch * ((wq == 0)  ? 0.5f : 1.0f);
        const float c3 = ch * ((wq == 15) ? 0.5f : 1.0f);
        const float w0 = (float)(wq * 4);

        const float a0 = c0 * t.x;
        const float a1 = ch * t.y;
        const float a2 = ch * t.z;
        const float a3 = c3 * t.w;
        const float a  = a0 + a1 + a2 + a3;

        s  += a;
        sh += (float)h * a;
        sw += a0 * w0 + a1 * (w0 + 1.0f) + a2 * (w0 + 2.0f) + a3 * (w0 + 3.0f);
    }

    // warp reduce
#pragma unroll
    for (int off = 16; off > 0; off >>= 1) {
        s  += __shfl_down_sync(0xffffffffu, s,  off);
        sw += __shfl_down_sync(0xffffffffu, sw, off);
        sh += __shfl_down_sync(0xffffffffu, sh, off);
    }
    __shared__ float sm[3][8];
    const int wid = tid >> 5, lid = tid & 31;
    if (lid == 0) { sm[0][wid] = s; sm[1][wid] = sw; sm[2][wid] = sh; }
    __syncthreads();
    if (tid == 0) {
        float a = 0.f, b = 0.f, c = 0.f;
#pragma unroll
        for (int i = 0; i < 8; ++i) { a += sm[0][i]; b += sm[1][i]; c += sm[2][i]; }
        const float x0 = vc[0];
        const float y0 = vc[1];
        const float dx = vc[2] - vc[0];                 // x spacing (ref's dx)
        const float dy = vc[2 * WW + 1] - vc[1];        // y spacing
        const float d2 = dx * dx;                       // ref uses dx for both axes
        g_iv[bi] = a * d2;
        g_j0[bi] = (x0 * a + dx * b) * d2;
        g_j1[bi] = (y0 * a + dy * c) * d2;
    }
}

// ---------------------------------------------------------------------------
// Kernel 2: fused combine + broadcast fill. One block per (b,o) plane.
// Phase A (256 threads):
//   warps 0-3: thread (f = wid, i = lane): partial S_d = Wx[f,o,i,d]*iv[b,i]
//   warps 4-7: thread (f, i):              partial C   = sum_d Wy[f,o,i,d]*J_d[b,i]
//   warp + smem reduce -> scalars s0, s1, c.
// Phase B: out[b,o,h,w] = s0*tc_x + s1*tc_y + c, with analytic separable tc.
//   4 float4 stores per thread (16 KB per block, 8 MB total).
// ---------------------------------------------------------------------------
__global__ __launch_bounds__(256) void frl_fill(
    const float* __restrict__ Wx, const float* __restrict__ Wy,
    const float* __restrict__ tc, float* __restrict__ out)
{
    const int bo = blockIdx.x;       // 0..511
    const int b  = bo >> 6;
    const int oo = bo & 63;
    const int tid = threadIdx.x;
    const int wid = tid >> 5, lid = tid & 31;

    __shared__ float part[3][8];

    // ---- Phase A: compute S0, S1, C for this (b, o) ----
    float p0 = 0.f, p1 = 0.f, pc = 0.f;
    {
        const int i = lid;
        const int f = wid & 3;
        const int w2idx = f * (CO * CI) + oo * CI + i;   // float2 index into [F,CO,CI,2]
        if (tid < 128) {
            const float2 t = reinterpret_cast<const float2*>(Wx)[w2idx];
            const float ivv = g_iv[b * CI + i];
            p0 = t.x * ivv;
            p1 = t.y * ivv;
        } else {
            const float2 t = reinterpret_cast<const float2*>(Wy)[w2idx];
            pc = t.x * g_j0[b * CI + i] + t.y * g_j1[b * CI + i];
        }
#pragma unroll
        for (int off = 16; off > 0; off >>= 1) {
            p0 += __shfl_down_sync(0xffffffffu, p0, off);
            p1 += __shfl_down_sync(0xffffffffu, p1, off);
            pc += __shfl_down_sync(0xffffffffu, pc, off);
        }
        if (lid == 0) { part[0][wid] = p0; part[1][wid] = p1; part[2][wid] = pc; }
    }
    __syncthreads();

    float s0 = 0.f, s1 = 0.f, c = 0.f;
#pragma unroll
    for (int i = 0; i < 8; ++i) { s0 += part[0][i]; s1 += part[1][i]; c += part[2][i]; }

    // ---- Phase B: broadcast fill with analytic target coords ----
    const float tx0 = tc[0];
    const float ty0 = tc[1];
    const float dtx = tc[2] - tc[0];
    const float dty = tc[2 * WW + 1] - tc[1];

    float4* __restrict__ out4 = reinterpret_cast<float4*>(out) + (size_t)bo * 1024;
    const float s0dx = s0 * dtx;

#pragma unroll
    for (int k = 0; k < 4; ++k) {
        const int q = tid + k * 256;       // float4 index in plane
        const int h  = q >> 4;
        const int wq = q & 15;
        const float ybase = fmaf(s1, fmaf((float)h, dty, ty0), c);
        const float xv = fmaf(s0, fmaf((float)(wq * 4), dtx, tx0), ybase);
        float4 r;
        r.x = xv;
        r.y = xv + s0dx;
        r.z = xv + 2.0f * s0dx;
        r.w = xv + 3.0f * s0dx;
        out4[q] = r;
    }
}

extern "C" void kernel_launch(void* const* d_in, const int* in_sizes, int n_in,
                              void* d_out, int out_size)
{
    const float* v   = (const float*)d_in[0];   // [B,CI,H,W]
    const float* vc  = (const float*)d_in[1];   // [H,W,2]
    const float* tc  = (const float*)d_in[2];   // [H,W,2]
    const float* Wx  = (const float*)d_in[3];   // [F,CO,CI,2]
    const float* Wy  = (const float*)d_in[4];   // [F,CO,CI,2]
    float* out = (float*)d_out;                  // [B,CO,H,W]

    (void)in_sizes; (void)n_in; (void)out_size;

    frl_reduce<<<BB * CI, 256>>>(v, vc);
    frl_fill  <<<BB * CO, 256>>>(Wx, Wy, tc, out);
}